// round 17
// baseline (speedup 1.0000x reference)
#include <cuda_runtime.h>
#include <cuda_bf16.h>

// Problem constants: B=2, H=1, LQ=LK=512, D=64, HID=128
#define NB   2
#define L    512
#define DD   64
#define HID  128

// Scratch (allocation-free rule: __device__ globals)
__device__ float  g_vp[NB * L * DD];             // projected V
__device__ float  g_qaqb[NB * L * HID * 2];      // interleaved (qa, qb) per (row, h)
__device__ float2 g_kbkaT[NB * HID * L];         // TRANSPOSED: [b][h][j] -> (kb+b1, ka+b1)
__device__ float  g_Cq[NB * L];                  // Σ_h (qa+qb)·w2/2 per q-row
__device__ float  g_Ck[NB * L];                  // Σ_h (kb'+ka')·w2/2 per k-row

// ---------------------------------------------------------------------------
// Kernel A: projections + pairwise-MLP feature precompute + rank-1 terms.
// grid = NB * (L/4) = 256 blocks, 256 threads.
// ---------------------------------------------------------------------------
__global__ __launch_bounds__(256) void prep_kernel(
    const float* __restrict__ q, const float* __restrict__ k,
    const float* __restrict__ v, const float* __restrict__ Ww,
    const float* __restrict__ wb, const float* __restrict__ W1,
    const float* __restrict__ b1, const float* __restrict__ W2)
{
    __shared__ float q_s[4][DD], k_s[4][DD], v_s[4][DD];
    __shared__ float qp_s[4][DD], kp_s[4][DD];
    __shared__ float red_c[8][4];        // per-warp partial rank-1 sums

    const int tid  = threadIdx.x;
    const int b    = blockIdx.x >> 7;
    const int r0   = (blockIdx.x & 127) * 4;
    const int base = (b * L + r0) * DD;

    {
        int r = tid >> 6, e = tid & 63;
        q_s[r][e] = q[base + tid];
        k_s[r][e] = k[base + tid];
        v_s[r][e] = v[base + tid];
    }
    __syncthreads();

    {
        int pj = tid >> 6, d = tid & 63;
        if (pj < 3) {
            const float (*src)[DD] = (pj == 0) ? q_s : (pj == 1) ? k_s : v_s;
            float acc[4];
            float bias = wb[d];
            #pragma unroll
            for (int r = 0; r < 4; r++) acc[r] = bias;
            #pragma unroll 8
            for (int e = 0; e < DD; e++) {
                float w = Ww[e * DD + d];
                #pragma unroll
                for (int r = 0; r < 4; r++) acc[r] += src[r][e] * w;
            }
            #pragma unroll
            for (int r = 0; r < 4; r++) {
                if (pj == 0)      qp_s[r][d] = acc[r];
                else if (pj == 1) kp_s[r][d] = acc[r];
                else              g_vp[base + r * DD + d] = acc[r];
            }
        }
    }
    __syncthreads();

    {
        int half = tid >> 7;     // 0: q-features, 1: k-features
        int h    = tid & 127;
        const float (*src)[DD] = half ? kp_s : qp_s;
        float accA[4] = {0.f, 0.f, 0.f, 0.f};   // · W1q
        float accB[4] = {0.f, 0.f, 0.f, 0.f};   // · W1k
        #pragma unroll 8
        for (int e = 0; e < DD; e++) {
            float w1q = W1[e * HID + h];
            float w1k = W1[(DD + e) * HID + h];
            #pragma unroll
            for (int r = 0; r < 4; r++) {
                float x = src[r][e];
                accA[r] += x * w1q;
                accB[r] += x * w1k;
            }
        }
        float bb = b1[h];
        float w2h = 0.5f * W2[h];
        float c[4];
        #pragma unroll
        for (int r = 0; r < 4; r++) {
            if (!half) {
                int off = ((b * L + r0 + r) * HID + h) * 2;
                g_qaqb[off + 0] = accA[r];                 // qa
                g_qaqb[off + 1] = accB[r];                 // qb
                c[r] = (accA[r] + accB[r]) * w2h;          // (qa+qb)·w2/2
            } else {
                float kb = accB[r] + bb, ka = accA[r] + bb;
                g_kbkaT[(b * HID + h) * L + (r0 + r)] = make_float2(kb, ka);
                c[r] = (kb + ka) * w2h;                    // (kb'+ka')·w2/2
            }
        }
        // block-reduce c over the 128 h of each half (4 warps per half)
        #pragma unroll
        for (int r = 0; r < 4; r++) {
            #pragma unroll
            for (int o = 16; o > 0; o >>= 1)
                c[r] += __shfl_xor_sync(0xffffffffu, c[r], o);
        }
        int warp = tid >> 5;
        if ((tid & 31) == 0) {
            #pragma unroll
            for (int r = 0; r < 4; r++) red_c[warp][r] = c[r];
        }
    }
    __syncthreads();

    if (tid < 8) {
        int half = tid >> 2, r = tid & 3;
        int w0 = half * 4;
        float s = red_c[w0][r] + red_c[w0 + 1][r] + red_c[w0 + 2][r] + red_c[w0 + 3][r];
        if (half == 0) g_Cq[b * L + r0 + r] = s;
        else           g_Ck[b * L + r0 + r] = s;
    }
}

// ---------------------------------------------------------------------------
// Kernel B: grid = NB*(L/4) = 256 blocks, 512 threads = 16 warps, 2 blocks/SM.
// Block covers 4 i-rows. Warp (jh, jq): jh = h-half, jq = j-slice of 64.
// Score loop: explicit 2-deep kk prefetch rotation (MLP 3-4); epilogue loads
// (Cq, Ck, mask) hoisted above the loop to overlap with compute.
// relu(x) = (x+|x|)/2 — rank-1 parts from prep, pairwise is FADD+FFMA(|t|).
// ---------------------------------------------------------------------------
__global__ __launch_bounds__(512, 2) void attn_kernel(
    const float* __restrict__ mask, const float* __restrict__ Wd,
    const float* __restrict__ db,   const float* __restrict__ W2,
    const float* __restrict__ b2,   float* __restrict__ out)
{
    __shared__ float4 qq_s[HID][2];      // per h: (qa,qb) rows 0,1 | rows 2,3
    __shared__ float  w2_s[HID];         // w2/2
    __shared__ float  attn_s[4][L];
    __shared__ float  sp[8][32][8];      // jh=1 partials [jq][lane][row*2+jp]
    __shared__ float  red_m[4][8], red_s[4][8];
    __shared__ float  o_part[4][16][DD];

    const int tid   = threadIdx.x;
    const int warp  = tid >> 5;
    const int lane  = tid & 31;
    const int jq    = warp & 7;          // j-slice
    const int jh    = warp >> 3;         // h-half
    const int b     = blockIdx.x >> 7;   // / 128
    const int itile = blockIdx.x & 127;
    const int row0  = b * L + itile * 4;
    const int jp    = jq * 32 + lane;    // j-pair index (j = 2*jp, 2*jp+1)

    // Stage q-features (4 rows) + W2/2
    if (tid < 256) {
        int h = tid >> 1, p = tid & 1;   // p: row-pair (0: rows 0-1, 1: rows 2-3)
        const float2* q2 = (const float2*)g_qaqb;
        float2 a0 = q2[(size_t)(row0 + 2 * p)     * HID + h];
        float2 a1 = q2[(size_t)(row0 + 2 * p + 1) * HID + h];
        qq_s[h][p] = make_float4(a0.x, a0.y, a1.x, a1.y);
    } else if (tid < 256 + HID) {
        w2_s[tid - 256] = 0.5f * W2[tid - 256];
    }

    // Hoisted epilogue loads — issue LDGs now, consume after the score loop.
    float2 ckv = __ldg((const float2*)(g_Ck + (size_t)b * L) + jp);
    float  cq[4];
    float2 mm[4];
    #pragma unroll
    for (int r = 0; r < 4; r++) {
        cq[r] = __ldg(g_Cq + row0 + r);
        mm[r] = __ldg((const float2*)(mask + (size_t)(row0 + r) * L) + jp);
    }
    const float b2v2 = 2.f * b2[0];
    __syncthreads();

    // ---- |.|-part of scores over own h-half, 2-deep explicit kk prefetch
    const float4* kt = reinterpret_cast<const float4*>(
        g_kbkaT + (size_t)(b * HID + jh * 64) * L) + jp;

    float acc[4][2];
    #pragma unroll
    for (int r = 0; r < 4; r++) { acc[r][0] = 0.f; acc[r][1] = 0.f; }

    float4 kk0 = __ldg(kt);
    float4 kk1 = __ldg(kt + (L / 2));

    #pragma unroll 2
    for (int hh = 0; hh < 64; hh++) {
        float4 kk = kk0;
        kk0 = kk1;
        if (hh + 2 < 64) kk1 = __ldg(kt + (hh + 2) * (L / 2));

        float4 q01 = qq_s[jh * 64 + hh][0];       // (qa0,qb0,qa1,qb1)
        float4 q23 = qq_s[jh * 64 + hh][1];       // (qa2,qb2,qa3,qb3)
        float  wh  = w2_s[jh * 64 + hh];

        acc[0][0] = fmaf(fabsf(q01.x + kk.x), wh, acc[0][0]);
        acc[0][0] = fmaf(fabsf(q01.y + kk.y), wh, acc[0][0]);
        acc[0][1] = fmaf(fabsf(q01.x + kk.z), wh, acc[0][1]);
        acc[0][1] = fmaf(fabsf(q01.y + kk.w), wh, acc[0][1]);
        acc[1][0] = fmaf(fabsf(q01.z + kk.x), wh, acc[1][0]);
        acc[1][0] = fmaf(fabsf(q01.w + kk.y), wh, acc[1][0]);
        acc[1][1] = fmaf(fabsf(q01.z + kk.z), wh, acc[1][1]);
        acc[1][1] = fmaf(fabsf(q01.w + kk.w), wh, acc[1][1]);
        acc[2][0] = fmaf(fabsf(q23.x + kk.x), wh, acc[2][0]);
        acc[2][0] = fmaf(fabsf(q23.y + kk.y), wh, acc[2][0]);
        acc[2][1] = fmaf(fabsf(q23.x + kk.z), wh, acc[2][1]);
        acc[2][1] = fmaf(fabsf(q23.y + kk.w), wh, acc[2][1]);
        acc[3][0] = fmaf(fabsf(q23.z + kk.x), wh, acc[3][0]);
        acc[3][0] = fmaf(fabsf(q23.w + kk.y), wh, acc[3][0]);
        acc[3][1] = fmaf(fabsf(q23.z + kk.z), wh, acc[3][1]);
        acc[3][1] = fmaf(fabsf(q23.w + kk.w), wh, acc[3][1]);
    }

    // combine h-halves: jh=1 dumps partials, jh=0 accumulates
    if (jh == 1) {
        #pragma unroll
        for (int r = 0; r < 4; r++) {
            sp[jq][lane][r * 2 + 0] = acc[r][0];
            sp[jq][lane][r * 2 + 1] = acc[r][1];
        }
    }
    __syncthreads();

    float s[4][2];
    if (jh == 0) {
        #pragma unroll
        for (int r = 0; r < 4; r++) {
            s[r][0] = acc[r][0] + sp[jq][lane][r * 2 + 0] + cq[r] + ckv.x + b2v2 + mm[r].x * (-1e9f);
            s[r][1] = acc[r][1] + sp[jq][lane][r * 2 + 1] + cq[r] + ckv.y + b2v2 + mm[r].y * (-1e9f);
        }

        float m[4];
        #pragma unroll
        for (int r = 0; r < 4; r++) {
            m[r] = fmaxf(s[r][0], s[r][1]);
            #pragma unroll
            for (int o = 16; o > 0; o >>= 1)
                m[r] = fmaxf(m[r], __shfl_xor_sync(0xffffffffu, m[r], o));
        }
        if (lane == 0) {
            #pragma unroll
            for (int r = 0; r < 4; r++) red_m[r][jq] = m[r];
        }
    }
    __syncthreads();

    if (jh == 0) {
        float sum[4];
        #pragma unroll
        for (int r = 0; r < 4; r++) {
            float g = red_m[r][0];
            #pragma unroll
            for (int w = 1; w < 8; w++) g = fmaxf(g, red_m[r][w]);
            s[r][0] = __expf(s[r][0] - g);
            s[r][1] = __expf(s[r][1] - g);
            float su = s[r][0] + s[r][1];
            #pragma unroll
            for (int o = 16; o > 0; o >>= 1)
                su += __shfl_xor_sync(0xffffffffu, su, o);
            sum[r] = su;
        }
        if (lane == 0) {
            #pragma unroll
            for (int r = 0; r < 4; r++) red_s[r][jq] = sum[r];
        }
    }
    __syncthreads();

    if (jh == 0) {
        float2* aout = (float2*)(out + (size_t)NB * L * DD + (size_t)row0 * L);
        #pragma unroll
        for (int r = 0; r < 4; r++) {
            float t = 0.f;
            #pragma unroll
            for (int w = 0; w < 8; w++) t += red_s[r][w];
            float inv = 1.f / t;
            float2 a = make_float2(s[r][0] * inv, s[r][1] * inv);
            ((float2*)attn_s[r])[jp] = a;
            aout[(size_t)r * (L / 2) + jp] = a;
        }
    }
    __syncthreads();

    // ---- attn @ vp: each of 16 warps covers 32 j; vv reused for 4 rows
    float ox[4], oy[4];
    #pragma unroll
    for (int r = 0; r < 4; r++) { ox[r] = 0.f; oy[r] = 0.f; }
    const float2* vp2 = (const float2*)(g_vp + (size_t)b * L * DD);
    #pragma unroll 2
    for (int jj = 0; jj < 32; jj++) {
        int j = warp * 32 + jj;
        float2 vv = __ldg(vp2 + j * 32 + lane);
        #pragma unroll
        for (int r = 0; r < 4; r++) {
            float a = attn_s[r][j];
            ox[r] += a * vv.x;
            oy[r] += a * vv.y;
        }
    }
    #pragma unroll
    for (int r = 0; r < 4; r++) {
        o_part[r][warp][2 * lane]     = ox[r];
        o_part[r][warp][2 * lane + 1] = oy[r];
    }
    __syncthreads();

    // ---- warps 0-3 reduce partials + output projection (warp w -> row w)
    if (warp < 4) {
        int r  = warp;
        int d0 = 2 * lane;
        float fox = 0.f, foy = 0.f;
        #pragma unroll
        for (int w = 0; w < 16; w++) {
            fox += o_part[r][w][d0];
            foy += o_part[r][w][d0 + 1];
        }
        o_part[r][0][d0]     = fox;
        o_part[r][0][d0 + 1] = foy;
        __syncwarp();

        float f0 = db[d0], f1 = db[d0 + 1];
        const float2* Wd2 = (const float2*)Wd;
        #pragma unroll 8
        for (int e = 0; e < DD; e++) {
            float ov = o_part[r][0][e];
            float2 wv = __ldg(Wd2 + e * 32 + lane);
            f0 += ov * wv.x;
            f1 += ov * wv.y;
        }
        out[(row0 + r) * DD + d0]     = f0;
        out[(row0 + r) * DD + d0 + 1] = f1;
    }
}

// ---------------------------------------------------------------------------
// Inputs (metadata order): q, k, v, mask, Ww, wb, Wd, db, W1, b1, W2, b2
// Output: [out (B,H,LQ,D) | attn (B,H,LQ,LK)] as float32
// ---------------------------------------------------------------------------
extern "C" void kernel_launch(void* const* d_in, const int* in_sizes, int n_in,
                              void* d_out, int out_size)
{
    const float* q    = (const float*)d_in[0];
    const float* k    = (const float*)d_in[1];
    const float* v    = (const float*)d_in[2];
    const float* mask = (const float*)d_in[3];
    const float* Ww   = (const float*)d_in[4];
    const float* wb   = (const float*)d_in[5];
    const float* Wd   = (const float*)d_in[6];
    const float* db   = (const float*)d_in[7];
    const float* W1   = (const float*)d_in[8];
    const float* b1   = (const float*)d_in[9];
    const float* W2   = (const float*)d_in[10];
    const float* b2   = (const float*)d_in[11];
    float* out = (float*)d_out;

    prep_kernel<<<NB * (L / 4), 256>>>(q, k, v, Ww, wb, W1, b1, W2);
    attn_kernel<<<NB * (L / 4), 512>>>(mask, Wd, db, W2, b2, out);
}